// round 1
// baseline (speedup 1.0000x reference)
#include <cuda_runtime.h>

#define BB 32
#define CC 256
#define TT 4096
#define NH 8
#define DH 64
#define DK 512   // NH*DH

// Scratch (allocation-free per harness rules)
__device__ float g_qW[BB * NH * CC];     // scale-folded q @ Wkv_k
__device__ float g_attn[BB * NH * TT];   // logits -> softmax in place
__device__ float g_xattn[BB * NH * CC];  // attn-weighted sum of x

// ---------------------------------------------------------------------------
// Kernel A: q = query@Wq.T + bq ; qW[b,n,c] = scale * sum_d q[n,d]*Wkv[n*64+d,c]
// grid = 32 (one per batch), 256 threads
// ---------------------------------------------------------------------------
__global__ void k_prep(const float* __restrict__ query,
                       const float* __restrict__ Wq,
                       const float* __restrict__ bq,
                       const float* __restrict__ Wkv) {
    const int b = blockIdx.x;
    const int tid = threadIdx.x;
    __shared__ float qin[CC];
    __shared__ float qs[DK];

    qin[tid] = query[b * CC + tid];
    __syncthreads();

    for (int nd = tid; nd < DK; nd += 256) {
        const float* wr = Wq + (size_t)nd * CC;
        float s = 0.f;
#pragma unroll 8
        for (int c = 0; c < CC; ++c) s += wr[c] * qin[c];
        qs[nd] = s + bq[nd];
    }
    __syncthreads();

    const float scale = 0.125f;  // 1/sqrt(D_HEAD=64)
    for (int o = tid; o < NH * CC; o += 256) {
        const int n = o >> 8;        // CC == 256
        const int c = o & 255;
        const float* qrow = qs + n * DH;
        const float* wcol = Wkv + (size_t)(n * DH) * CC + c;
        float s = 0.f;
#pragma unroll 8
        for (int d = 0; d < DH; ++d) s += qrow[d] * wcol[(size_t)d * CC];
        g_qW[b * NH * CC + o] = s * scale;
    }
}

// ---------------------------------------------------------------------------
// Kernel B: logits[b,n,j] = sum_c qW[b,n,c] * x[b,c,j]   (first x sweep)
// grid = (8 j-tiles of 512, 32 b), 128 threads, 4 j per thread via float4
// ---------------------------------------------------------------------------
__global__ void k_logits(const float* __restrict__ x) {
    const int b = blockIdx.y;
    const int j0 = blockIdx.x * 512;
    const int tid = threadIdx.x;

    __shared__ float qw[NH][CC];
    for (int i = tid; i < NH * CC; i += 128) qw[i >> 8][i & 255] = g_qW[b * NH * CC + i];
    __syncthreads();

    float4 acc[NH];
#pragma unroll
    for (int n = 0; n < NH; ++n) acc[n] = make_float4(0.f, 0.f, 0.f, 0.f);

    const float4* xp = (const float4*)(x + (size_t)b * CC * TT + j0) + tid;
#pragma unroll 4
    for (int c = 0; c < CC; ++c) {
        const float4 xv = xp[(size_t)c * (TT / 4)];
#pragma unroll
        for (int n = 0; n < NH; ++n) {
            const float w = qw[n][c];
            acc[n].x += w * xv.x; acc[n].y += w * xv.y;
            acc[n].z += w * xv.z; acc[n].w += w * xv.w;
        }
    }
#pragma unroll
    for (int n = 0; n < NH; ++n)
        ((float4*)(g_attn + (size_t)(b * NH + n) * TT + j0))[tid] = acc[n];
}

// ---------------------------------------------------------------------------
// Kernel C: softmax over j=4096, in place. grid = 256 rows, 256 threads
// ---------------------------------------------------------------------------
__global__ void k_softmax() {
    const int row = blockIdx.x;
    const int tid = threadIdx.x;
    float4* p = (float4*)(g_attn + (size_t)row * TT);

    float4 v[4];
#pragma unroll
    for (int i = 0; i < 4; ++i) v[i] = p[tid + i * 256];

    float m = -1e30f;
#pragma unroll
    for (int i = 0; i < 4; ++i)
        m = fmaxf(m, fmaxf(fmaxf(v[i].x, v[i].y), fmaxf(v[i].z, v[i].w)));

    __shared__ float red[8];
#pragma unroll
    for (int o = 16; o; o >>= 1) m = fmaxf(m, __shfl_xor_sync(~0u, m, o));
    if ((tid & 31) == 0) red[tid >> 5] = m;
    __syncthreads();
    m = red[0];
#pragma unroll
    for (int i = 1; i < 8; ++i) m = fmaxf(m, red[i]);
    __syncthreads();

    float s = 0.f;
#pragma unroll
    for (int i = 0; i < 4; ++i) {
        v[i].x = __expf(v[i].x - m); v[i].y = __expf(v[i].y - m);
        v[i].z = __expf(v[i].z - m); v[i].w = __expf(v[i].w - m);
        s += v[i].x + v[i].y + v[i].z + v[i].w;
    }
#pragma unroll
    for (int o = 16; o; o >>= 1) s += __shfl_xor_sync(~0u, s, o);
    if ((tid & 31) == 0) red[tid >> 5] = s;
    __syncthreads();
    s = red[0];
#pragma unroll
    for (int i = 1; i < 8; ++i) s += red[i];

    const float inv = 1.f / s;
#pragma unroll
    for (int i = 0; i < 4; ++i) {
        v[i].x *= inv; v[i].y *= inv; v[i].z *= inv; v[i].w *= inv;
        p[tid + i * 256] = v[i];
    }
}

// ---------------------------------------------------------------------------
// Kernel D: xattn[b,n,c] = sum_j attn[b,n,j] * x[b,c,j]   (second x sweep)
// grid = (8 c-tiles of 32, 32 b), 256 threads = 8 warps, warp owns 4 c-values
// ---------------------------------------------------------------------------
__global__ void k_xattn(const float* __restrict__ x) {
    const int b = blockIdx.y;
    const int cbase = blockIdx.x * 32 + (threadIdx.x >> 5) * 4;
    const int tid = threadIdx.x;
    const int lane = tid & 31;

    __shared__ float4 attn_s[NH][256];  // one 1024-j chunk, 32 KB

    float acc[NH][4];
#pragma unroll
    for (int n = 0; n < NH; ++n)
#pragma unroll
        for (int cc = 0; cc < 4; ++cc) acc[n][cc] = 0.f;

    const float4* ap = (const float4*)(g_attn + (size_t)b * NH * TT);

    for (int chunk = 0; chunk < 4; ++chunk) {
        const int jq0 = chunk * 256;  // float4 index of chunk start
        __syncthreads();
        for (int i = tid; i < NH * 256; i += 256)
            attn_s[i >> 8][i & 255] = ap[(i >> 8) * (TT / 4) + jq0 + (i & 255)];
        __syncthreads();

        const float4* xp = (const float4*)(x + (size_t)b * CC * TT) + jq0;
#pragma unroll 2
        for (int step = 0; step < 8; ++step) {
            const int q = lane + step * 32;
            float4 xv[4];
#pragma unroll
            for (int cc = 0; cc < 4; ++cc)
                xv[cc] = xp[(size_t)(cbase + cc) * (TT / 4) + q];
#pragma unroll
            for (int n = 0; n < NH; ++n) {
                const float4 av = attn_s[n][q];
#pragma unroll
                for (int cc = 0; cc < 4; ++cc)
                    acc[n][cc] += av.x * xv[cc].x + av.y * xv[cc].y +
                                  av.z * xv[cc].z + av.w * xv[cc].w;
            }
        }
    }

#pragma unroll
    for (int n = 0; n < NH; ++n)
#pragma unroll
        for (int cc = 0; cc < 4; ++cc) {
            float v = acc[n][cc];
#pragma unroll
            for (int o = 16; o; o >>= 1) v += __shfl_xor_sync(~0u, v, o);
            if (lane == 0) g_xattn[(size_t)(b * NH + n) * CC + cbase + cc] = v;
        }
}

// ---------------------------------------------------------------------------
// Kernel E: oh[nd] = Wkv_v[nd]·xattn[b,n] + bkv_v ; y = relu(oh@Wfc.T + bfc)
// grid = 32, 256 threads
// ---------------------------------------------------------------------------
__global__ void k_out(const float* __restrict__ Wkv,
                      const float* __restrict__ bkv,
                      const float* __restrict__ Wfc,
                      const float* __restrict__ bfc,
                      float* __restrict__ out) {
    const int b = blockIdx.x;
    const int tid = threadIdx.x;
    __shared__ float xa[NH * CC];
    __shared__ float oh[DK];

    for (int i = tid; i < NH * CC; i += 256) xa[i] = g_xattn[b * NH * CC + i];
    __syncthreads();

    for (int nd = tid; nd < DK; nd += 256) {
        const int n = nd >> 6;
        const float* wr = Wkv + (size_t)(DK + nd) * CC;  // v rows start at DK
        const float* xr = xa + n * CC;
        float s = 0.f;
#pragma unroll 8
        for (int c = 0; c < CC; ++c) s += wr[c] * xr[c];
        oh[nd] = s + bkv[DK + nd];
    }
    __syncthreads();

    const float* wr = Wfc + (size_t)tid * DK;
    float s = 0.f;
#pragma unroll 8
    for (int k = 0; k < DK; ++k) s += wr[k] * oh[k];
    s += bfc[tid];
    out[b * CC + tid] = fmaxf(s, 0.f);
}

// ---------------------------------------------------------------------------
extern "C" void kernel_launch(void* const* d_in, const int* in_sizes, int n_in,
                              void* d_out, int out_size) {
    const float* x     = (const float*)d_in[0];  // (32,256,64,64)
    const float* query = (const float*)d_in[1];  // (32,256)
    const float* Wkv   = (const float*)d_in[2];  // (1024,256)
    const float* bkv   = (const float*)d_in[3];  // (1024)
    const float* Wq    = (const float*)d_in[4];  // (512,256)
    const float* bq    = (const float*)d_in[5];  // (512)
    const float* Wfc   = (const float*)d_in[6];  // (256,512)
    const float* bfc   = (const float*)d_in[7];  // (256)
    float* out = (float*)d_out;                  // (32,256)

    k_prep<<<BB, 256>>>(query, Wq, bq, Wkv);
    k_logits<<<dim3(TT / 512, BB), 128>>>(x);
    k_softmax<<<BB * NH, 256>>>();
    k_xattn<<<dim3(CC / 32, BB), 256>>>(x);
    k_out<<<BB, 256>>>(Wkv, bkv, Wfc, bfc, out);
}

// round 2
// speedup vs baseline: 1.6011x; 1.6011x over previous
#include <cuda_runtime.h>

#define BB 32
#define CC 256
#define TT 4096
#define NH 8
#define DH 64
#define DK 512   // NH*DH

// Scratch (allocation-free per harness rules)
__device__ float g_qW[BB * NH * CC];     // scale-folded q @ Wkv_k
__device__ float g_p0[BB * NH * TT];     // partial logits, c in [0,128)
__device__ float g_p1[BB * NH * TT];     // partial logits, c in [128,256)
__device__ float g_attn[BB * NH * TT];   // softmax output
__device__ float g_xattn[BB * NH * CC];  // attn-weighted sum of x

// ---------------------------------------------------------------------------
// Kernel A: q = query@Wq.T + bq ; qW[b,n,c] = scale * sum_d q[n,d]*Wkv[n*64+d,c]
// grid = 32, 256 threads. Warp-per-row coalesced dot for Wq.
// ---------------------------------------------------------------------------
__global__ void k_prep(const float* __restrict__ query,
                       const float* __restrict__ Wq,
                       const float* __restrict__ bq,
                       const float* __restrict__ Wkv) {
    const int b = blockIdx.x;
    const int tid = threadIdx.x, wid = tid >> 5, lane = tid & 31;
    __shared__ float qin[CC];
    __shared__ float qs[DK];

    qin[tid] = query[b * CC + tid];
    __syncthreads();

    const float4* qv = (const float4*)qin;
    for (int nd = wid; nd < DK; nd += 8) {
        const float4* wr = (const float4*)(Wq + (size_t)nd * CC);
        float s = 0.f;
#pragma unroll
        for (int i = 0; i < 2; ++i) {
            const float4 w = wr[lane + i * 32];
            const float4 q4 = qv[lane + i * 32];
            s += w.x * q4.x + w.y * q4.y + w.z * q4.z + w.w * q4.w;
        }
#pragma unroll
        for (int o = 16; o; o >>= 1) s += __shfl_xor_sync(~0u, s, o);
        if (!lane) qs[nd] = s + bq[nd];
    }
    __syncthreads();

    const float scale = 0.125f;  // 1/sqrt(64)
    for (int o = tid; o < NH * CC; o += 256) {
        const int n = o >> 8;
        const int c = o & 255;
        const float* qrow = qs + n * DH;
        const float* wcol = Wkv + (size_t)(n * DH) * CC + c;
        float s = 0.f;
#pragma unroll 8
        for (int d = 0; d < DH; ++d) s += qrow[d] * wcol[(size_t)d * CC];
        g_qW[b * NH * CC + o] = s * scale;
    }
}

// ---------------------------------------------------------------------------
// Kernel B: partial logits, c split in halves across blockIdx.y.
// grid = (4 j-tiles of 1024, 2 c-halves, 32 b), 256 threads.
// ---------------------------------------------------------------------------
__global__ void __launch_bounds__(256) k_logits(const float* __restrict__ x) {
    const int b = blockIdx.z;
    const int ch = blockIdx.y;                       // c half: 0 or 1
    const int jq = blockIdx.x * 256 + threadIdx.x;   // float4 index into j

    __shared__ float4 qwT[128][2];                   // [c][n-quad]
    for (int i = threadIdx.x; i < 128 * NH; i += 256) {
        const int c = i >> 3, n = i & 7;
        ((float*)&qwT[c][0])[n] = g_qW[b * NH * CC + n * CC + ch * 128 + c];
    }
    __syncthreads();

    float4 acc[NH];
#pragma unroll
    for (int n = 0; n < NH; ++n) acc[n] = make_float4(0.f, 0.f, 0.f, 0.f);

    const float4* xp = (const float4*)(x + ((size_t)b * CC + ch * 128) * TT) + jq;
#pragma unroll 4
    for (int c = 0; c < 128; ++c) {
        const float4 xv = xp[(size_t)c * (TT / 4)];
        const float4 w0 = qwT[c][0];
        const float4 w1 = qwT[c][1];
        acc[0].x += w0.x * xv.x; acc[0].y += w0.x * xv.y; acc[0].z += w0.x * xv.z; acc[0].w += w0.x * xv.w;
        acc[1].x += w0.y * xv.x; acc[1].y += w0.y * xv.y; acc[1].z += w0.y * xv.z; acc[1].w += w0.y * xv.w;
        acc[2].x += w0.z * xv.x; acc[2].y += w0.z * xv.y; acc[2].z += w0.z * xv.z; acc[2].w += w0.z * xv.w;
        acc[3].x += w0.w * xv.x; acc[3].y += w0.w * xv.y; acc[3].z += w0.w * xv.z; acc[3].w += w0.w * xv.w;
        acc[4].x += w1.x * xv.x; acc[4].y += w1.x * xv.y; acc[4].z += w1.x * xv.z; acc[4].w += w1.x * xv.w;
        acc[5].x += w1.y * xv.x; acc[5].y += w1.y * xv.y; acc[5].z += w1.y * xv.z; acc[5].w += w1.y * xv.w;
        acc[6].x += w1.z * xv.x; acc[6].y += w1.z * xv.y; acc[6].z += w1.z * xv.z; acc[6].w += w1.z * xv.w;
        acc[7].x += w1.w * xv.x; acc[7].y += w1.w * xv.y; acc[7].z += w1.w * xv.z; acc[7].w += w1.w * xv.w;
    }

    float* base = ch ? g_p1 : g_p0;
#pragma unroll
    for (int n = 0; n < NH; ++n)
        ((float4*)(base + (size_t)(b * NH + n) * TT))[jq] = acc[n];
}

// ---------------------------------------------------------------------------
// Kernel C: logits = p0 + p1, softmax over j=4096. grid = 256 rows, 256 threads
// ---------------------------------------------------------------------------
__global__ void k_softmax() {
    const int row = blockIdx.x;
    const int tid = threadIdx.x;
    const float4* p0 = (const float4*)(g_p0 + (size_t)row * TT);
    const float4* p1 = (const float4*)(g_p1 + (size_t)row * TT);
    float4* pa = (float4*)(g_attn + (size_t)row * TT);

    float4 v[4];
#pragma unroll
    for (int i = 0; i < 4; ++i) {
        const float4 a = p0[tid + i * 256];
        const float4 b = p1[tid + i * 256];
        v[i] = make_float4(a.x + b.x, a.y + b.y, a.z + b.z, a.w + b.w);
    }

    float m = -1e30f;
#pragma unroll
    for (int i = 0; i < 4; ++i)
        m = fmaxf(m, fmaxf(fmaxf(v[i].x, v[i].y), fmaxf(v[i].z, v[i].w)));

    __shared__ float red[8];
#pragma unroll
    for (int o = 16; o; o >>= 1) m = fmaxf(m, __shfl_xor_sync(~0u, m, o));
    if ((tid & 31) == 0) red[tid >> 5] = m;
    __syncthreads();
    m = red[0];
#pragma unroll
    for (int i = 1; i < 8; ++i) m = fmaxf(m, red[i]);
    __syncthreads();

    float s = 0.f;
#pragma unroll
    for (int i = 0; i < 4; ++i) {
        v[i].x = __expf(v[i].x - m); v[i].y = __expf(v[i].y - m);
        v[i].z = __expf(v[i].z - m); v[i].w = __expf(v[i].w - m);
        s += v[i].x + v[i].y + v[i].z + v[i].w;
    }
#pragma unroll
    for (int o = 16; o; o >>= 1) s += __shfl_xor_sync(~0u, s, o);
    if ((tid & 31) == 0) red[tid >> 5] = s;
    __syncthreads();
    s = red[0];
#pragma unroll
    for (int i = 1; i < 8; ++i) s += red[i];

    const float inv = 1.f / s;
#pragma unroll
    for (int i = 0; i < 4; ++i) {
        v[i].x *= inv; v[i].y *= inv; v[i].z *= inv; v[i].w *= inv;
        pa[tid + i * 256] = v[i];
    }
}

// ---------------------------------------------------------------------------
// Kernel D: xattn[b,n,c] = sum_j attn[b,n,j] * x[b,c,j]   (second x sweep)
// grid = (8 c-tiles of 32, 32 b), 256 threads = 8 warps, warp owns 4 c-values.
// j-step unrolled x2 for 8 LDGs in flight.
// ---------------------------------------------------------------------------
__global__ void __launch_bounds__(256) k_xattn(const float* __restrict__ x) {
    const int b = blockIdx.y;
    const int cbase = blockIdx.x * 32 + (threadIdx.x >> 5) * 4;
    const int tid = threadIdx.x;
    const int lane = tid & 31;

    __shared__ float4 attn_s[NH][256];  // one 1024-j chunk, 32 KB

    float acc[NH][4];
#pragma unroll
    for (int n = 0; n < NH; ++n)
#pragma unroll
        for (int cc = 0; cc < 4; ++cc) acc[n][cc] = 0.f;

    const float4* ap = (const float4*)(g_attn + (size_t)b * NH * TT);

    for (int chunk = 0; chunk < 4; ++chunk) {
        const int jq0 = chunk * 256;  // float4 index of chunk start
        __syncthreads();
        for (int i = tid; i < NH * 256; i += 256)
            attn_s[i >> 8][i & 255] = ap[(i >> 8) * (TT / 4) + jq0 + (i & 255)];
        __syncthreads();

        const float4* xp = (const float4*)(x + (size_t)b * CC * TT) + jq0;
#pragma unroll
        for (int step = 0; step < 8; step += 2) {
            const int q1 = lane + step * 32;
            const int q2 = q1 + 32;
            float4 xv1[4], xv2[4];
#pragma unroll
            for (int cc = 0; cc < 4; ++cc) {
                xv1[cc] = xp[(size_t)(cbase + cc) * (TT / 4) + q1];
                xv2[cc] = xp[(size_t)(cbase + cc) * (TT / 4) + q2];
            }
#pragma unroll
            for (int n = 0; n < NH; ++n) {
                const float4 a1 = attn_s[n][q1];
                const float4 a2 = attn_s[n][q2];
#pragma unroll
                for (int cc = 0; cc < 4; ++cc) {
                    acc[n][cc] += a1.x * xv1[cc].x + a1.y * xv1[cc].y +
                                  a1.z * xv1[cc].z + a1.w * xv1[cc].w;
                    acc[n][cc] += a2.x * xv2[cc].x + a2.y * xv2[cc].y +
                                  a2.z * xv2[cc].z + a2.w * xv2[cc].w;
                }
            }
        }
    }

#pragma unroll
    for (int n = 0; n < NH; ++n)
#pragma unroll
        for (int cc = 0; cc < 4; ++cc) {
            float v = acc[n][cc];
#pragma unroll
            for (int o = 16; o; o >>= 1) v += __shfl_xor_sync(~0u, v, o);
            if (lane == 0) g_xattn[(size_t)(b * NH + n) * CC + cbase + cc] = v;
        }
}

// ---------------------------------------------------------------------------
// Kernel E: oh[nd] = Wkv_v[nd]·xattn[b,n] + bkv_v ; y = relu(oh@Wfc.T + bfc)
// grid = 32, 256 threads. Warp-per-row coalesced dots.
// ---------------------------------------------------------------------------
__global__ void k_out(const float* __restrict__ Wkv,
                      const float* __restrict__ bkv,
                      const float* __restrict__ Wfc,
                      const float* __restrict__ bfc,
                      float* __restrict__ out) {
    const int b = blockIdx.x;
    const int tid = threadIdx.x, wid = tid >> 5, lane = tid & 31;
    __shared__ float xa[NH * CC];
    __shared__ float oh[DK];

    for (int i = tid; i < NH * CC; i += 256) xa[i] = g_xattn[b * NH * CC + i];
    __syncthreads();

    for (int nd = wid; nd < DK; nd += 8) {
        const float4* wr = (const float4*)(Wkv + (size_t)(DK + nd) * CC);  // v rows
        const float4* xr = (const float4*)(xa + (nd >> 6) * CC);
        float s = 0.f;
#pragma unroll
        for (int i = 0; i < 2; ++i) {
            const float4 w = wr[lane + i * 32];
            const float4 v = xr[lane + i * 32];
            s += w.x * v.x + w.y * v.y + w.z * v.z + w.w * v.w;
        }
#pragma unroll
        for (int o = 16; o; o >>= 1) s += __shfl_xor_sync(~0u, s, o);
        if (!lane) oh[nd] = s + bkv[DK + nd];
    }
    __syncthreads();

    const float4* ov = (const float4*)oh;
    for (int o = wid; o < CC; o += 8) {
        const float4* wr = (const float4*)(Wfc + (size_t)o * DK);
        float s = 0.f;
#pragma unroll
        for (int i = 0; i < 4; ++i) {
            const float4 w = wr[lane + i * 32];
            const float4 v = ov[lane + i * 32];
            s += w.x * v.x + w.y * v.y + w.z * v.z + w.w * v.w;
        }
#pragma unroll
        for (int oo = 16; oo; oo >>= 1) s += __shfl_xor_sync(~0u, s, oo);
        if (!lane) out[b * CC + o] = fmaxf(s + bfc[o], 0.f);
    }
}

// ---------------------------------------------------------------------------
extern "C" void kernel_launch(void* const* d_in, const int* in_sizes, int n_in,
                              void* d_out, int out_size) {
    const float* x     = (const float*)d_in[0];  // (32,256,64,64)
    const float* query = (const float*)d_in[1];  // (32,256)
    const float* Wkv   = (const float*)d_in[2];  // (1024,256)
    const float* bkv   = (const float*)d_in[3];  // (1024)
    const float* Wq    = (const float*)d_in[4];  // (512,256)
    const float* bq    = (const float*)d_in[5];  // (512)
    const float* Wfc   = (const float*)d_in[6];  // (256,512)
    const float* bfc   = (const float*)d_in[7];  // (256)
    float* out = (float*)d_out;                  // (32,256)

    k_prep<<<BB, 256>>>(query, Wq, bq, Wkv);
    k_logits<<<dim3(TT / 1024, 2, BB), 256>>>(x);
    k_softmax<<<BB * NH, 256>>>();
    k_xattn<<<dim3(CC / 32, BB), 256>>>(x);
    k_out<<<BB, 256>>>(Wkv, bkv, Wfc, bfc, out);
}

// round 4
// speedup vs baseline: 3.8593x; 2.4103x over previous
#include <cuda_runtime.h>

#define BB 32
#define CC 256
#define TT 4096
#define NH 8
#define DH 64
#define DK 512   // NH*DH

// Scratch (allocation-free per harness rules)
__device__ float g_qW[BB * NH * CC];        // scale-folded q @ Wkv_k
__device__ float g_pl[4][BB * NH * TT];     // partial logits, 4 c-quarters
__device__ float g_attn[BB * NH * TT];      // softmax output
__device__ float g_xp[2][BB * NH * CC];     // xattn partials, 2 j-halves

// ---------------------------------------------------------------------------
// Kernel A: per (n,b): q[n,:] = query@Wq.T + bq ; qW[b,n,c] = scale * q·Wkv_k[:,c]
// grid = (8 n, 32 b), 256 threads
// ---------------------------------------------------------------------------
__global__ void k_prep(const float* __restrict__ query,
                       const float* __restrict__ Wq,
                       const float* __restrict__ bq,
                       const float* __restrict__ Wkv) {
    const int n = blockIdx.x, b = blockIdx.y;
    const int tid = threadIdx.x, wid = tid >> 5, lane = tid & 31;
    __shared__ float qin[CC];
    __shared__ float qs[DH];

    qin[tid] = query[b * CC + tid];
    __syncthreads();

    // Phase 1: q[n*64+d] for d in [0,64) — warp per row
    const float4* qv = (const float4*)qin;
    for (int d = wid; d < DH; d += 8) {
        const float4* wr = (const float4*)(Wq + (size_t)(n * DH + d) * CC);
        float s = 0.f;
#pragma unroll
        for (int i = 0; i < 2; ++i) {
            const float4 w = wr[lane + i * 32];
            const float4 q4 = qv[lane + i * 32];
            s += w.x * q4.x + w.y * q4.y + w.z * q4.z + w.w * q4.w;
        }
#pragma unroll
        for (int o = 16; o; o >>= 1) s += __shfl_xor_sync(~0u, s, o);
        if (!lane) qs[d] = s + bq[n * DH + d];
    }
    __syncthreads();

    // Phase 2: thread per c — coalesced Wkv column walk
    const float* wbase = Wkv + (size_t)(n * DH) * CC + tid;
    float s = 0.f;
#pragma unroll 8
    for (int d = 0; d < DH; ++d) s += qs[d] * wbase[(size_t)d * CC];
    g_qW[(b * NH + n) * CC + tid] = s * 0.125f;  // 1/sqrt(64)
}

// ---------------------------------------------------------------------------
// Kernel B: partial logits, c split in quarters across blockIdx.y.
// grid = (4 j-tiles of 1024, 4 c-quarters, 32 b), 256 threads.
// ---------------------------------------------------------------------------
__global__ void __launch_bounds__(256) k_logits(const float* __restrict__ x) {
    const int b = blockIdx.z;
    const int cq = blockIdx.y;                       // c quarter
    const int jq = blockIdx.x * 256 + threadIdx.x;   // float4 index into j

    __shared__ float4 qwT[64][2];                    // [c][n-quad], 512 floats
    for (int i = threadIdx.x; i < 64 * NH; i += 256) {
        const int c = i >> 3, n = i & 7;
        ((float*)&qwT[c][0])[n] = g_qW[(b * NH + n) * CC + cq * 64 + c];
    }
    __syncthreads();

    float4 acc[NH];
#pragma unroll
    for (int n = 0; n < NH; ++n) acc[n] = make_float4(0.f, 0.f, 0.f, 0.f);

    const float4* xp = (const float4*)(x + ((size_t)b * CC + cq * 64) * TT) + jq;
#pragma unroll 8
    for (int c = 0; c < 64; ++c) {
        const float4 xv = __ldcs(&xp[(size_t)c * (TT / 4)]);
        const float4 w0 = qwT[c][0];
        const float4 w1 = qwT[c][1];
        acc[0].x += w0.x * xv.x; acc[0].y += w0.x * xv.y; acc[0].z += w0.x * xv.z; acc[0].w += w0.x * xv.w;
        acc[1].x += w0.y * xv.x; acc[1].y += w0.y * xv.y; acc[1].z += w0.y * xv.z; acc[1].w += w0.y * xv.w;
        acc[2].x += w0.z * xv.x; acc[2].y += w0.z * xv.y; acc[2].z += w0.z * xv.z; acc[2].w += w0.z * xv.w;
        acc[3].x += w0.w * xv.x; acc[3].y += w0.w * xv.y; acc[3].z += w0.w * xv.z; acc[3].w += w0.w * xv.w;
        acc[4].x += w1.x * xv.x; acc[4].y += w1.x * xv.y; acc[4].z += w1.x * xv.z; acc[4].w += w1.x * xv.w;
        acc[5].x += w1.y * xv.x; acc[5].y += w1.y * xv.y; acc[5].z += w1.y * xv.z; acc[5].w += w1.y * xv.w;
        acc[6].x += w1.z * xv.x; acc[6].y += w1.z * xv.y; acc[6].z += w1.z * xv.z; acc[6].w += w1.z * xv.w;
        acc[7].x += w1.w * xv.x; acc[7].y += w1.w * xv.y; acc[7].z += w1.w * xv.z; acc[7].w += w1.w * xv.w;
    }

#pragma unroll
    for (int n = 0; n < NH; ++n)
        ((float4*)(g_pl[cq] + (size_t)(b * NH + n) * TT))[jq] = acc[n];
}

// ---------------------------------------------------------------------------
// Kernel C: logits = sum of 4 partials, softmax over j=4096.
// grid = 256 rows, 256 threads
// ---------------------------------------------------------------------------
__global__ void k_softmax() {
    const int row = blockIdx.x;
    const int tid = threadIdx.x;
    float4* pa = (float4*)(g_attn + (size_t)row * TT);

    float4 v[4];
#pragma unroll
    for (int i = 0; i < 4; ++i) {
        float4 a = ((const float4*)(g_pl[0] + (size_t)row * TT))[tid + i * 256];
#pragma unroll
        for (int p = 1; p < 4; ++p) {
            const float4 c = ((const float4*)(g_pl[p] + (size_t)row * TT))[tid + i * 256];
            a.x += c.x; a.y += c.y; a.z += c.z; a.w += c.w;
        }
        v[i] = a;
    }

    float m = -1e30f;
#pragma unroll
    for (int i = 0; i < 4; ++i)
        m = fmaxf(m, fmaxf(fmaxf(v[i].x, v[i].y), fmaxf(v[i].z, v[i].w)));

    __shared__ float red[8];
#pragma unroll
    for (int o = 16; o; o >>= 1) m = fmaxf(m, __shfl_xor_sync(~0u, m, o));
    if ((tid & 31) == 0) red[tid >> 5] = m;
    __syncthreads();
    m = red[0];
#pragma unroll
    for (int i = 1; i < 8; ++i) m = fmaxf(m, red[i]);
    __syncthreads();

    float s = 0.f;
#pragma unroll
    for (int i = 0; i < 4; ++i) {
        v[i].x = __expf(v[i].x - m); v[i].y = __expf(v[i].y - m);
        v[i].z = __expf(v[i].z - m); v[i].w = __expf(v[i].w - m);
        s += v[i].x + v[i].y + v[i].z + v[i].w;
    }
#pragma unroll
    for (int o = 16; o; o >>= 1) s += __shfl_xor_sync(~0u, s, o);
    if ((tid & 31) == 0) red[tid >> 5] = s;
    __syncthreads();
    s = red[0];
#pragma unroll
    for (int i = 1; i < 8; ++i) s += red[i];

    const float inv = 1.f / s;
#pragma unroll
    for (int i = 0; i < 4; ++i) {
        v[i].x *= inv; v[i].y *= inv; v[i].z *= inv; v[i].w *= inv;
        pa[tid + i * 256] = v[i];
    }
}

// ---------------------------------------------------------------------------
// Kernel D: xattn partial over j-half. grid = (8 c-tiles, 2 j-halves, 32 b),
// 256 threads = 8 warps, warp owns 4 c. 2 chunks of 1024 j per block.
// ---------------------------------------------------------------------------
__global__ void __launch_bounds__(256) k_xattn(const float* __restrict__ x) {
    const int b = blockIdx.z;
    const int jh = blockIdx.y;
    const int cbase = blockIdx.x * 32 + (threadIdx.x >> 5) * 4;
    const int tid = threadIdx.x;
    const int lane = tid & 31;

    __shared__ float4 attn_s[NH][256];  // one 1024-j chunk, 32 KB

    float acc[NH][4];
#pragma unroll
    for (int n = 0; n < NH; ++n)
#pragma unroll
        for (int cc = 0; cc < 4; ++cc) acc[n][cc] = 0.f;

    const float4* ap = (const float4*)(g_attn + (size_t)b * NH * TT);

    for (int chunk = 0; chunk < 2; ++chunk) {
        const int jq0 = jh * 512 + chunk * 256;  // float4 index of chunk start
        __syncthreads();
        for (int i = tid; i < NH * 256; i += 256)
            attn_s[i >> 8][i & 255] = ap[(i >> 8) * (TT / 4) + jq0 + (i & 255)];
        __syncthreads();

        const float4* xp = (const float4*)(x + (size_t)b * CC * TT) + jq0;
#pragma unroll
        for (int step = 0; step < 8; step += 2) {
            const int q1 = lane + step * 32;
            const int q2 = q1 + 32;
            float4 xv1[4], xv2[4];
#pragma unroll
            for (int cc = 0; cc < 4; ++cc) {
                xv1[cc] = __ldcs(&xp[(size_t)(cbase + cc) * (TT / 4) + q1]);
                xv2[cc] = __ldcs(&xp[(size_t)(cbase + cc) * (TT / 4) + q2]);
            }
#pragma unroll
            for (int n = 0; n < NH; ++n) {
                const float4 a1 = attn_s[n][q1];
                const float4 a2 = attn_s[n][q2];
#pragma unroll
                for (int cc = 0; cc < 4; ++cc) {
                    acc[n][cc] += a1.x * xv1[cc].x + a1.y * xv1[cc].y +
                                  a1.z * xv1[cc].z + a1.w * xv1[cc].w;
                    acc[n][cc] += a2.x * xv2[cc].x + a2.y * xv2[cc].y +
                                  a2.z * xv2[cc].z + a2.w * xv2[cc].w;
                }
            }
        }
    }

#pragma unroll
    for (int n = 0; n < NH; ++n)
#pragma unroll
        for (int cc = 0; cc < 4; ++cc) {
            float v = acc[n][cc];
#pragma unroll
            for (int o = 16; o; o >>= 1) v += __shfl_xor_sync(~0u, v, o);
            if (lane == 0) g_xp[jh][(size_t)(b * NH + n) * CC + cbase + cc] = v;
        }
}

// ---------------------------------------------------------------------------
// Kernel E: oh[nd] = Wkv_v[nd]·xattn[b,n] + bkv_v ; y = relu(oh@Wfc.T + bfc)
// grid = 32, 512 threads. Warp-per-row coalesced dots.
// ---------------------------------------------------------------------------
__global__ void __launch_bounds__(512) k_out(const float* __restrict__ Wkv,
                      const float* __restrict__ bkv,
                      const float* __restrict__ Wfc,
                      const float* __restrict__ bfc,
                      float* __restrict__ out) {
    const int b = blockIdx.x;
    const int tid = threadIdx.x, wid = tid >> 5, lane = tid & 31;
    __shared__ float xa[NH * CC];
    __shared__ float oh[DK];

    for (int i = tid; i < NH * CC; i += 512)
        xa[i] = g_xp[0][b * NH * CC + i] + g_xp[1][b * NH * CC + i];
    __syncthreads();

    for (int nd = wid; nd < DK; nd += 16) {
        const float4* wr = (const float4*)(Wkv + (size_t)(DK + nd) * CC);  // v rows
        const float4* xr = (const float4*)(xa + (nd >> 6) * CC);
        float s = 0.f;
#pragma unroll
        for (int i = 0; i < 2; ++i) {
            const float4 w = wr[lane + i * 32];
            const float4 v = xr[lane + i * 32];
            s += w.x * v.x + w.y * v.y + w.z * v.z + w.w * v.w;
        }
#pragma unroll
        for (int o = 16; o; o >>= 1) s += __shfl_xor_sync(~0u, s, o);
        if (!lane) oh[nd] = s + bkv[DK + nd];
    }
    __syncthreads();

    const float4* ov = (const float4*)oh;
    for (int o = wid; o < CC; o += 16) {
        const float4* wr = (const float4*)(Wfc + (size_t)o * DK);
        float s = 0.f;
#pragma unroll
        for (int i = 0; i < 4; ++i) {
            const float4 w = wr[lane + i * 32];
            const float4 v = ov[lane + i * 32];
            s += w.x * v.x + w.y * v.y + w.z * v.z + w.w * v.w;
        }
#pragma unroll
        for (int oo = 16; oo; oo >>= 1) s += __shfl_xor_sync(~0u, s, oo);
        if (!lane) out[b * CC + o] = fmaxf(s + bfc[o], 0.f);
    }
}

// ---------------------------------------------------------------------------
extern "C" void kernel_launch(void* const* d_in, const int* in_sizes, int n_in,
                              void* d_out, int out_size) {
    const float* x     = (const float*)d_in[0];  // (32,256,64,64)
    const float* query = (const float*)d_in[1];  // (32,256)
    const float* Wkv   = (const float*)d_in[2];  // (1024,256)
    const float* bkv   = (const float*)d_in[3];  // (1024)
    const float* Wq    = (const float*)d_in[4];  // (512,256)
    const float* bq    = (const float*)d_in[5];  // (512)
    const float* Wfc   = (const float*)d_in[6];  // (256,512)
    const float* bfc   = (const float*)d_in[7];  // (256)
    float* out = (float*)d_out;                  // (32,256)

    k_prep<<<dim3(NH, BB), 256>>>(query, Wq, bq, Wkv);
    k_logits<<<dim3(TT / 1024, 4, BB), 256>>>(x);
    k_softmax<<<BB * NH, 256>>>();
    k_xattn<<<dim3(CC / 32, 2, BB), 256>>>(x);
    k_out<<<BB, 512>>>(Wkv, bkv, Wfc, bfc, out);
}